// round 9
// baseline (speedup 1.0000x reference)
#include <cuda_runtime.h>
#include <cstdint>

// Problem constants
#define BB 8
#define SS 1024
#define DD 768
#define HH 12
#define LL 6
#define DF 3072
#define HD 64
#define TD 2304   // 3*D
#define NROWS (BB*SS)   // 8192

// ---------------- scratch (static device globals; no allocs allowed) -------------
__device__ float g_x[NROWS * DD];                 // residual stream
__device__ float g_h[NROWS * DD];                 // layernorm output
__device__ float g_qkv[NROWS * TD];               // qkv projection
__device__ float g_att[NROWS * DD];               // attention output
__device__ float g_ff[NROWS * DF];                // ff1 output

// ---------------- helpers --------------------------------------------------------
__device__ __forceinline__ uint32_t f2tf(float f) {
    uint32_t u;
    asm("cvt.rna.tf32.f32 %0, %1;" : "=r"(u) : "f"(f));
    return u;
}

#define MMA_TF32(c, a, b)                                                        \
    asm volatile(                                                                \
        "mma.sync.aligned.m16n8k8.row.col.f32.tf32.tf32.f32 "                    \
        "{%0,%1,%2,%3},{%4,%5,%6,%7},{%8,%9},{%0,%1,%2,%3};"                     \
        : "+f"((c)[0]), "+f"((c)[1]), "+f"((c)[2]), "+f"((c)[3])                 \
        : "r"((a)[0]), "r"((a)[1]), "r"((a)[2]), "r"((a)[3]),                    \
          "r"((b)[0]), "r"((b)[1]))

#define CP_ASYNC16(dst, src)                                                     \
    asm volatile("cp.async.cg.shared.global [%0], [%1], 16;" :: "r"(dst), "l"(src))
#define CP_COMMIT() asm volatile("cp.async.commit_group;")
#define CP_WAIT(n)  asm volatile("cp.async.wait_group %0;" :: "n"(n))

// Convert a uint4 of fp32 bits to tf32 bits in place
__device__ __forceinline__ uint4 cvt4(uint4 v) {
    v.x = f2tf(__uint_as_float(v.x));
    v.y = f2tf(__uint_as_float(v.y));
    v.z = f2tf(__uint_as_float(v.z));
    v.w = f2tf(__uint_as_float(v.w));
    return v;
}

// ---------------- embedding ------------------------------------------------------
__global__ void embed_kernel(const int* __restrict__ ids,
                             const float* __restrict__ tok,
                             const float* __restrict__ pos,
                             float* __restrict__ x) {
    int idx = blockIdx.x * blockDim.x + threadIdx.x;
    if (idx >= NROWS * DD) return;
    int bs = idx / DD;
    int d  = idx - bs * DD;
    int s  = bs & (SS - 1);
    x[idx] = (tok[(size_t)ids[bs] * DD + d] + pos[s * DD + d]) * 27.712812921102035f;
}

// ---------------- layernorm (block per row, 768 = 256*3) --------------------------
__global__ __launch_bounds__(256) void ln_kernel(const float* __restrict__ x,
                                                 const float* __restrict__ sc,
                                                 const float* __restrict__ bi,
                                                 float* __restrict__ out) {
    int row = blockIdx.x;
    int tid = threadIdx.x;
    const float* p = x + (size_t)row * DD;
    float v0 = p[tid], v1 = p[tid + 256], v2 = p[tid + 512];
    __shared__ float rs[256], rq[256];
    rs[tid] = v0 + v1 + v2;
    rq[tid] = v0 * v0 + v1 * v1 + v2 * v2;
    __syncthreads();
    for (int st = 128; st > 0; st >>= 1) {
        if (tid < st) { rs[tid] += rs[tid + st]; rq[tid] += rq[tid + st]; }
        __syncthreads();
    }
    float mean = rs[0] * (1.0f / DD);
    float var  = rq[0] * (1.0f / DD) - mean * mean;
    float inv  = rsqrtf(var + 1e-5f);
    float* o = out + (size_t)row * DD;
    o[tid]       = (v0 - mean) * inv * sc[tid]       + bi[tid];
    o[tid + 256] = (v1 - mean) * inv * sc[tid + 256] + bi[tid + 256];
    o[tid + 512] = (v2 - mean) * inv * sc[tid + 512] + bi[tid + 512];
}

// ---------------- tf32 GEMM v3: cp.async double-buffered + smem tf32 convert -----
// C[M,N] = A[M,K] @ B[K,N] + bias (+relu)(+res).  BM=128, BN=128, BK=32.
// Whole tile converted fp32->tf32 in smem once per k-tile; inner loop is pure LDS+MMA.
#define TG_ASTR 36
#define TG_BSTR 136
#define TG_ABUF (128 * TG_ASTR)            // 4608 words
#define TG_BBUF (32 * TG_BSTR)             // 4352 words
#define TG_BUF  9216                       // padded to 2304 uint4 (A+B = 8960 used)
#define TG_SMEM (2 * TG_BUF * 4)           // 73728 bytes

template <bool RELU, bool RES>
__global__ __launch_bounds__(256, 2) void tgemm2(
    const float* __restrict__ A, const float* __restrict__ B,
    const float* __restrict__ bias, const float* __restrict__ res,
    float* __restrict__ C, int K, int N)
{
    constexpr int BK = 32;
    extern __shared__ float sm[];
    const uint32_t sbase = (uint32_t)__cvta_generic_to_shared(sm);

    const int tid = threadIdx.x;
    const int bm = blockIdx.y * 128;
    const int bn = blockIdx.x * 128;
    const int wid = tid >> 5, lane = tid & 31;
    const int gid = lane >> 2, tig = lane & 3;
    const int wn = (wid & 3) * 32;
    const int wm = (wid >> 2) * 64;

    const float* Ab = A + (size_t)bm * K;

    float acc[4][4][4];
#pragma unroll
    for (int mi = 0; mi < 4; mi++)
#pragma unroll
        for (int ni = 0; ni < 4; ni++)
#pragma unroll
            for (int q = 0; q < 4; q++) acc[mi][ni][q] = 0.f;

    auto issue = [&](int kt, int p) {
        int k0 = kt * BK;
#pragma unroll
        for (int i = 0; i < 4; i++) {
            int f = i * 256 + tid;
            int r = f >> 3, kq = f & 7;
            uint32_t d = sbase + (uint32_t)(p * TG_BUF + r * TG_ASTR + kq * 4) * 4;
            CP_ASYNC16(d, Ab + (size_t)r * K + k0 + kq * 4);
        }
#pragma unroll
        for (int i = 0; i < 4; i++) {
            int f = i * 256 + tid;
            int kr = f >> 5, nq = f & 31;
            uint32_t d = sbase + (uint32_t)(p * TG_BUF + TG_ABUF + kr * TG_BSTR + nq * 4) * 4;
            CP_ASYNC16(d, B + (size_t)(k0 + kr) * N + bn + nq * 4);
        }
        CP_COMMIT();
    };

    issue(0, 0);

    const int KT = K / BK;
    for (int kt = 0; kt < KT; kt++) {
        const int p = kt & 1;
        if (kt + 1 < KT) { issue(kt + 1, p ^ 1); CP_WAIT(1); }
        else             { CP_WAIT(0); }
        __syncthreads();

        // ---- convert whole tile fp32 -> tf32 in smem (vectorized, once) ----
        {
            uint4* buf = (uint4*)(sm + p * TG_BUF);
#pragma unroll
            for (int i = 0; i < 9; i++)
                buf[i * 256 + tid] = cvt4(buf[i * 256 + tid]);
        }
        __syncthreads();

        const uint32_t* As = (const uint32_t*)(sm + p * TG_BUF);
        const uint32_t* Bs = As + TG_ABUF;
#pragma unroll
        for (int ks = 0; ks < BK; ks += 8) {
            uint32_t af[4][4], bf[4][2];
#pragma unroll
            for (int mi = 0; mi < 4; mi++) {
                int m = wm + mi * 16 + gid;
                af[mi][0] = As[m * TG_ASTR + ks + tig];
                af[mi][1] = As[(m + 8) * TG_ASTR + ks + tig];
                af[mi][2] = As[m * TG_ASTR + ks + tig + 4];
                af[mi][3] = As[(m + 8) * TG_ASTR + ks + tig + 4];
            }
#pragma unroll
            for (int ni = 0; ni < 4; ni++) {
                int n = wn + ni * 8 + gid;
                bf[ni][0] = Bs[(ks + tig) * TG_BSTR + n];
                bf[ni][1] = Bs[(ks + tig + 4) * TG_BSTR + n];
            }
#pragma unroll
            for (int mi = 0; mi < 4; mi++)
#pragma unroll
                for (int ni = 0; ni < 4; ni++)
                    MMA_TF32(acc[mi][ni], af[mi], bf[ni]);
        }
        __syncthreads();
    }

    // ---- epilogue ----
#pragma unroll
    for (int mi = 0; mi < 4; mi++) {
        int r0 = bm + wm + mi * 16 + gid;
#pragma unroll
        for (int ni = 0; ni < 4; ni++) {
            int c = bn + wn + ni * 8 + tig * 2;
            float b0 = bias[c], b1 = bias[c + 1];
            float v0 = acc[mi][ni][0] + b0;
            float v1 = acc[mi][ni][1] + b1;
            float v2 = acc[mi][ni][2] + b0;
            float v3 = acc[mi][ni][3] + b1;
            if (RELU) {
                v0 = fmaxf(v0, 0.f); v1 = fmaxf(v1, 0.f);
                v2 = fmaxf(v2, 0.f); v3 = fmaxf(v3, 0.f);
            }
            if (RES) {
                const float* rp0 = res + (size_t)r0 * N + c;
                const float* rp1 = res + (size_t)(r0 + 8) * N + c;
                v0 += rp0[0]; v1 += rp0[1];
                v2 += rp1[0]; v3 += rp1[1];
            }
            float2 w0 = { v0, v1 };
            float2 w1 = { v2, v3 };
            *(float2*)(C + (size_t)r0 * N + c) = w0;
            *(float2*)(C + (size_t)(r0 + 8) * N + c) = w1;
        }
    }
}

// ---------------- fused flash attention v3 ---------------------------------------
// One CTA per (128 q-rows, b, h). cp.async double-buffered K/V, whole-tile tf32
// convert in smem. Smem words: Ps 8704 | KV 2x9216 | msk 1024.
#define FA_PS    0
#define FA_KV    8704
#define FA_KVBUF 9216                       // one K+V pair (words)
#define FA_MSK   (FA_KV + 2 * FA_KVBUF)     // 27136
#define FA_WORDS (FA_MSK + 1024)            // 28160
#define FA_SMEM  (FA_WORDS * 4)             // 112640 bytes

__global__ __launch_bounds__(256, 2) void fattn_kernel(
    const float* __restrict__ qkv, const int* __restrict__ mask,
    float* __restrict__ att)
{
    extern __shared__ float sm[];
    const uint32_t sbase = (uint32_t)__cvta_generic_to_shared(sm);
    uint32_t (*Ps)[68] = (uint32_t(*)[68])sm;
    int* msk = (int*)(sm + FA_MSK);

    const int bh = blockIdx.y, b = bh / HH, h = bh % HH;
    const int s0 = blockIdx.x * 128;
    const int tid = threadIdx.x, wid = tid >> 5, lane = tid & 31;
    const int gid = lane >> 2, tig = lane & 3;

    const float* Qg = qkv + (size_t)(b * SS + s0) * TD + h * 192;
    const float* Kg = qkv + (size_t)b * SS * TD + h * 192 + 64;
    const float* Vg = Kg + 64;

    // K/V cp.async mapping: 64 rows x 16 float4; 4 threads/row, 4 float4 each
    const int pr = tid >> 2;
    const int pc = (tid & 3) * 4;

    auto issueKV = [&](int tc, int p) {
        int t0 = tc * 64;
        const float* kp = Kg + (size_t)(t0 + pr) * TD;
        const float* vp = Vg + (size_t)(t0 + pr) * TD;
        uint32_t kd = sbase + (uint32_t)(FA_KV + p * FA_KVBUF + pr * 72) * 4;
        uint32_t vd = kd + 4608 * 4;
#pragma unroll
        for (int i = 0; i < 4; i++) {
            CP_ASYNC16(kd + (pc + i) * 16, kp + (pc + i) * 4);
            CP_ASYNC16(vd + (pc + i) * 16, vp + (pc + i) * 4);
        }
        CP_COMMIT();
    };

    issueKV(0, 0);

    // ---- preload mask row (1024 ints) ----
    ((int4*)msk)[tid] = ((const int4*)(mask + b * SS))[tid];

    // ---- stage Q (128x64) via Ps into A-fragments ----
    {
        int r = tid >> 1;
        int c0 = (tid & 1) * 8;
#pragma unroll
        for (int i = 0; i < 8; i++) {
            float4 v = *(const float4*)(Qg + (size_t)r * TD + (c0 + i) * 4);
            uint4 u = { f2tf(v.x), f2tf(v.y), f2tf(v.z), f2tf(v.w) };
            *(uint4*)(&Ps[r][(c0 + i) * 4]) = u;
        }
    }
    __syncthreads();
    uint32_t qf[8][4];
    {
        int m = wid * 16 + gid;
#pragma unroll
        for (int kt = 0; kt < 8; kt++) {
            qf[kt][0] = Ps[m][kt * 8 + tig];
            qf[kt][1] = Ps[m + 8][kt * 8 + tig];
            qf[kt][2] = Ps[m][kt * 8 + tig + 4];
            qf[kt][3] = Ps[m + 8][kt * 8 + tig + 4];
        }
    }
    __syncthreads();   // Q frags loaded before Ps reused for P

    float of[8][4];
#pragma unroll
    for (int ni = 0; ni < 8; ni++)
#pragma unroll
        for (int q = 0; q < 4; q++) of[ni][q] = 0.f;
    float mrun0 = -INFINITY, mrun1 = -INFINITY;
    float lrun0 = 0.f, lrun1 = 0.f;

    for (int tc = 0; tc < SS / 64; tc++) {
        const int p = tc & 1;
        if (tc + 1 < SS / 64) { issueKV(tc + 1, p ^ 1); CP_WAIT(1); }
        else                  { CP_WAIT(0); }
        __syncthreads();

        // ---- convert K+V tile fp32 -> tf32 in smem (vectorized, once) ----
        {
            uint4* buf = (uint4*)(sm + FA_KV + p * FA_KVBUF);
#pragma unroll
            for (int i = 0; i < 9; i++)
                buf[i * 256 + tid] = cvt4(buf[i * 256 + tid]);
        }
        __syncthreads();

        const uint32_t (*Kf)[72] = (const uint32_t(*)[72])(sm + FA_KV + p * FA_KVBUF);
        const uint32_t (*Vf)[72] = Kf + 64;
        const int* mt = msk + tc * 64;

        // ---- S = Q @ K^T ----
        float sf[8][4];
#pragma unroll
        for (int ni = 0; ni < 8; ni++)
#pragma unroll
            for (int q = 0; q < 4; q++) sf[ni][q] = 0.f;
#pragma unroll
        for (int kt = 0; kt < 8; kt++) {
#pragma unroll
            for (int ni = 0; ni < 8; ni++) {
                uint32_t bf[2];
                bf[0] = Kf[ni * 8 + gid][kt * 8 + tig];
                bf[1] = Kf[ni * 8 + gid][kt * 8 + tig + 4];
                MMA_TF32(sf[ni], qf[kt], bf);
            }
        }

        // ---- mask + scale + online softmax ----
        float mnew0 = mrun0, mnew1 = mrun1;
#pragma unroll
        for (int ni = 0; ni < 8; ni++) {
            int c = ni * 8 + 2 * tig;
            bool m0 = mt[c] == 1, m1 = mt[c + 1] == 1;
            sf[ni][0] = m0 ? -1e9f : sf[ni][0] * 0.125f;
            sf[ni][1] = m1 ? -1e9f : sf[ni][1] * 0.125f;
            sf[ni][2] = m0 ? -1e9f : sf[ni][2] * 0.125f;
            sf[ni][3] = m1 ? -1e9f : sf[ni][3] * 0.125f;
            mnew0 = fmaxf(mnew0, fmaxf(sf[ni][0], sf[ni][1]));
            mnew1 = fmaxf(mnew1, fmaxf(sf[ni][2], sf[ni][3]));
        }
        mnew0 = fmaxf(mnew0, __shfl_xor_sync(0xffffffffu, mnew0, 1));
        mnew0 = fmaxf(mnew0, __shfl_xor_sync(0xffffffffu, mnew0, 2));
        mnew1 = fmaxf(mnew1, __shfl_xor_sync(0xffffffffu, mnew1, 1));
        mnew1 = fmaxf(mnew1, __shfl_xor_sync(0xffffffffu, mnew1, 2));
        float alpha0 = __expf(mrun0 - mnew0);
        float alpha1 = __expf(mrun1 - mnew1);
        mrun0 = mnew0; mrun1 = mnew1;

        float rs0 = 0.f, rs1 = 0.f;
#pragma unroll
        for (int ni = 0; ni < 8; ni++) {
            sf[ni][0] = __expf(sf[ni][0] - mnew0);
            sf[ni][1] = __expf(sf[ni][1] - mnew0);
            sf[ni][2] = __expf(sf[ni][2] - mnew1);
            sf[ni][3] = __expf(sf[ni][3] - mnew1);
            rs0 += sf[ni][0] + sf[ni][1];
            rs1 += sf[ni][2] + sf[ni][3];
        }
        rs0 += __shfl_xor_sync(0xffffffffu, rs0, 1);
        rs0 += __shfl_xor_sync(0xffffffffu, rs0, 2);
        rs1 += __shfl_xor_sync(0xffffffffu, rs1, 1);
        rs1 += __shfl_xor_sync(0xffffffffu, rs1, 2);
        lrun0 = lrun0 * alpha0 + rs0;
        lrun1 = lrun1 * alpha1 + rs1;
#pragma unroll
        for (int ni = 0; ni < 8; ni++) {
            of[ni][0] *= alpha0; of[ni][1] *= alpha0;
            of[ni][2] *= alpha1; of[ni][3] *= alpha1;
        }

        // ---- write P (tf32) to own rows of Ps ----
        {
            int r0 = wid * 16 + gid;
#pragma unroll
            for (int ni = 0; ni < 8; ni++) {
                int c = ni * 8 + 2 * tig;
                uint2 u0 = { f2tf(sf[ni][0]), f2tf(sf[ni][1]) };
                *(uint2*)(&Ps[r0][c]) = u0;
                uint2 u1 = { f2tf(sf[ni][2]), f2tf(sf[ni][3]) };
                *(uint2*)(&Ps[r0 + 8][c]) = u1;
            }
        }

        // ---- O += P @ V (reads only this warp's P rows) ----
        {
            int m = wid * 16 + gid;
#pragma unroll
            for (int kt = 0; kt < 8; kt++) {
                uint32_t a[4];
                a[0] = Ps[m][kt * 8 + tig];
                a[1] = Ps[m + 8][kt * 8 + tig];
                a[2] = Ps[m][kt * 8 + tig + 4];
                a[3] = Ps[m + 8][kt * 8 + tig + 4];
#pragma unroll
                for (int ni = 0; ni < 8; ni++) {
                    uint32_t bf[2];
                    bf[0] = Vf[kt * 8 + tig][ni * 8 + gid];
                    bf[1] = Vf[kt * 8 + tig + 4][ni * 8 + gid];
                    MMA_TF32(of[ni], a, bf);
                }
            }
        }
        __syncthreads();   // all reads of this K/V buffer done before overwrite
    }

    // ---- epilogue: O /= l, write to att ----
    float inv0 = 1.f / lrun0;
    float inv1 = 1.f / lrun1;
    int r0 = s0 + wid * 16 + gid;
#pragma unroll
    for (int ni = 0; ni < 8; ni++) {
        int c = h * 64 + ni * 8 + 2 * tig;
        float2 v0 = { of[ni][0] * inv0, of[ni][1] * inv0 };
        *(float2*)(att + (size_t)(b * SS + r0) * DD + c) = v0;
        float2 v1 = { of[ni][2] * inv1, of[ni][3] * inv1 };
        *(float2*)(att + (size_t)(b * SS + r0 + 8) * DD + c) = v1;
    }
}

// ---------------- final head: LN(x[:,0,:]) @ cls_w + cls_b ------------------------
__global__ __launch_bounds__(256) void head_kernel(const float* __restrict__ x,
                                                   const float* __restrict__ hs,
                                                   const float* __restrict__ hb,
                                                   const float* __restrict__ cw,
                                                   const float* __restrict__ cb,
                                                   float* __restrict__ out) {
    int b = blockIdx.x;
    int tid = threadIdx.x;
    const float* p = x + (size_t)b * SS * DD;   // s = 0 row
    float v0 = p[tid], v1 = p[tid + 256], v2 = p[tid + 512];
    __shared__ float rs[256], rq[256];
    rs[tid] = v0 + v1 + v2;
    rq[tid] = v0 * v0 + v1 * v1 + v2 * v2;
    __syncthreads();
    for (int st = 128; st > 0; st >>= 1) {
        if (tid < st) { rs[tid] += rs[tid + st]; rq[tid] += rq[tid + st]; }
        __syncthreads();
    }
    float mean = rs[0] * (1.0f / DD);
    float var  = rq[0] * (1.0f / DD) - mean * mean;
    float inv  = rsqrtf(var + 1e-5f);
    float p0 = (v0 - mean) * inv * hs[tid]       + hb[tid];
    float p1 = (v1 - mean) * inv * hs[tid + 256] + hb[tid + 256];
    float p2 = (v2 - mean) * inv * hs[tid + 512] + hb[tid + 512];
    float d0 = p0 * cw[2 * tid]     + p1 * cw[2 * (tid + 256)]     + p2 * cw[2 * (tid + 512)];
    float d1 = p0 * cw[2 * tid + 1] + p1 * cw[2 * (tid + 256) + 1] + p2 * cw[2 * (tid + 512) + 1];
    __syncthreads();
    rs[tid] = d0; rq[tid] = d1;
    __syncthreads();
    for (int st = 128; st > 0; st >>= 1) {
        if (tid < st) { rs[tid] += rs[tid + st]; rq[tid] += rq[tid + st]; }
        __syncthreads();
    }
    if (tid == 0) {
        out[2 * b]     = rs[0] + cb[0];
        out[2 * b + 1] = rq[0] + cb[1];
    }
}

// ---------------- host orchestration ---------------------------------------------
extern "C" void kernel_launch(void* const* d_in, const int* in_sizes, int n_in,
                              void* d_out, int out_size) {
    const int*   input_ids = (const int*)d_in[0];
    const int*   attn_mask = (const int*)d_in[1];
    const float* token_emb = (const float*)d_in[2];
    const float* pos_emb   = (const float*)d_in[3];
    const float* qkv_w     = (const float*)d_in[4];
    const float* qkv_b     = (const float*)d_in[5];
    const float* out_w     = (const float*)d_in[6];
    const float* out_b     = (const float*)d_in[7];
    const float* n1_s      = (const float*)d_in[8];
    const float* n1_b      = (const float*)d_in[9];
    const float* ff1_w     = (const float*)d_in[10];
    const float* ff1_b     = (const float*)d_in[11];
    const float* ff2_w     = (const float*)d_in[12];
    const float* ff2_b     = (const float*)d_in[13];
    const float* n2_s      = (const float*)d_in[14];
    const float* n2_b      = (const float*)d_in[15];
    const float* hln_s     = (const float*)d_in[16];
    const float* hln_b     = (const float*)d_in[17];
    const float* cls_w     = (const float*)d_in[18];
    const float* cls_b     = (const float*)d_in[19];
    float* out = (float*)d_out;

    float *x, *h, *qkv, *att, *ff;
    cudaGetSymbolAddress((void**)&x,   g_x);
    cudaGetSymbolAddress((void**)&h,   g_h);
    cudaGetSymbolAddress((void**)&qkv, g_qkv);
    cudaGetSymbolAddress((void**)&att, g_att);
    cudaGetSymbolAddress((void**)&ff,  g_ff);

    cudaFuncSetAttribute(fattn_kernel,
                         cudaFuncAttributeMaxDynamicSharedMemorySize, FA_SMEM);
    cudaFuncSetAttribute(tgemm2<false, false>,
                         cudaFuncAttributeMaxDynamicSharedMemorySize, TG_SMEM);
    cudaFuncSetAttribute(tgemm2<false, true>,
                         cudaFuncAttributeMaxDynamicSharedMemorySize, TG_SMEM);
    cudaFuncSetAttribute(tgemm2<true, false>,
                         cudaFuncAttributeMaxDynamicSharedMemorySize, TG_SMEM);

    embed_kernel<<<(NROWS * DD + 255) / 256, 256>>>(input_ids, token_emb, pos_emb, x);

    for (int i = 0; i < LL; i++) {
        ln_kernel<<<NROWS, 256>>>(x, n1_s + i * DD, n1_b + i * DD, h);
        // QKV projection: [8192,768] @ [768,2304]
        tgemm2<false, false><<<dim3(TD / 128, NROWS / 128), 256, TG_SMEM>>>(
            h, qkv_w + (size_t)i * DD * TD, qkv_b + i * TD, nullptr, qkv, DD, TD);
        // fused attention: scores + softmax + P@V, no DRAM score tensor
        fattn_kernel<<<dim3(SS / 128, BB * HH), 256, FA_SMEM>>>(qkv, attn_mask, att);
        // out projection + residual
        tgemm2<false, true><<<dim3(DD / 128, NROWS / 128), 256, TG_SMEM>>>(
            att, out_w + (size_t)i * DD * DD, out_b + i * DD, x, x, DD, DD);
        ln_kernel<<<NROWS, 256>>>(x, n2_s + i * DD, n2_b + i * DD, h);
        // FF1 + relu
        tgemm2<true, false><<<dim3(DF / 128, NROWS / 128), 256, TG_SMEM>>>(
            h, ff1_w + (size_t)i * DD * DF, ff1_b + i * DF, nullptr, ff, DD, DF);
        // FF2 + residual
        tgemm2<false, true><<<dim3(DD / 128, NROWS / 128), 256, TG_SMEM>>>(
            ff, ff2_w + (size_t)i * DF * DD, ff2_b + i * DD, x, x, DF, DD);
    }

    head_kernel<<<BB, 256>>>(x, hln_s, hln_b, cls_w, cls_b, out);
}

// round 10
// speedup vs baseline: 1.2419x; 1.2419x over previous
#include <cuda_runtime.h>
#include <cstdint>

// Problem constants
#define BB 8
#define SS 1024
#define DD 768
#define HH 12
#define LL 6
#define DF 3072
#define HD 64
#define TD 2304   // 3*D
#define NROWS (BB*SS)   // 8192

// ---------------- scratch (static device globals; no allocs allowed) -------------
__device__ float g_x[NROWS * DD];                 // residual stream (fp32)
__device__ float g_h[NROWS * DD];                 // layernorm output (tf32 bits)
__device__ float g_qkv[NROWS * TD];               // qkv projection (tf32 bits)
__device__ float g_att[NROWS * DD];               // attention output (tf32 bits)
__device__ float g_ff[NROWS * DF];                // ff1 output (tf32 bits)

// converted (tf32-bit) weights
#define W_QKV 0
#define W_OUT (LL * DD * TD)                       // 10616832
#define W_FF1 (W_OUT + LL * DD * DD)               // 14155776
#define W_FF2 (W_FF1 + LL * DD * DF)               // 28311552
#define W_TOT (W_FF2 + LL * DF * DD)               // 42467328
__device__ float g_wt[W_TOT];

// ---------------- helpers --------------------------------------------------------
__device__ __forceinline__ uint32_t f2tf(float f) {
    uint32_t u;
    asm("cvt.rna.tf32.f32 %0, %1;" : "=r"(u) : "f"(f));
    return u;
}

#define MMA_TF32(c, a, b)                                                        \
    asm volatile(                                                                \
        "mma.sync.aligned.m16n8k8.row.col.f32.tf32.tf32.f32 "                    \
        "{%0,%1,%2,%3},{%4,%5,%6,%7},{%8,%9},{%0,%1,%2,%3};"                     \
        : "+f"((c)[0]), "+f"((c)[1]), "+f"((c)[2]), "+f"((c)[3])                 \
        : "r"((a)[0]), "r"((a)[1]), "r"((a)[2]), "r"((a)[3]),                    \
          "r"((b)[0]), "r"((b)[1]))

#define CP_ASYNC16(dst, src)                                                     \
    asm volatile("cp.async.cg.shared.global [%0], [%1], 16;" :: "r"(dst), "l"(src))
#define CP_COMMIT() asm volatile("cp.async.commit_group;")
#define CP_WAIT(n)  asm volatile("cp.async.wait_group %0;" :: "n"(n))

// ---------------- weight conversion (fp32 -> tf32 bits), vectorized --------------
__global__ __launch_bounds__(256) void cvtw_kernel(const float* __restrict__ in,
                                                   float* __restrict__ out, int n4) {
    int i = blockIdx.x * blockDim.x + threadIdx.x;
    if (i >= n4) return;
    uint4 v = ((const uint4*)in)[i];
    v.x = f2tf(__uint_as_float(v.x));
    v.y = f2tf(__uint_as_float(v.y));
    v.z = f2tf(__uint_as_float(v.z));
    v.w = f2tf(__uint_as_float(v.w));
    ((uint4*)out)[i] = v;
}

// ---------------- embedding ------------------------------------------------------
__global__ void embed_kernel(const int* __restrict__ ids,
                             const float* __restrict__ tok,
                             const float* __restrict__ pos,
                             float* __restrict__ x) {
    int idx = blockIdx.x * blockDim.x + threadIdx.x;
    if (idx >= NROWS * DD) return;
    int bs = idx / DD;
    int d  = idx - bs * DD;
    int s  = bs & (SS - 1);
    x[idx] = (tok[(size_t)ids[bs] * DD + d] + pos[s * DD + d]) * 27.712812921102035f;
}

// ---------------- layernorm: fp32 in, tf32-bit out --------------------------------
__global__ __launch_bounds__(256) void ln_kernel(const float* __restrict__ x,
                                                 const float* __restrict__ sc,
                                                 const float* __restrict__ bi,
                                                 float* __restrict__ out) {
    int row = blockIdx.x;
    int tid = threadIdx.x;
    const float* p = x + (size_t)row * DD;
    float v0 = p[tid], v1 = p[tid + 256], v2 = p[tid + 512];
    __shared__ float rs[256], rq[256];
    rs[tid] = v0 + v1 + v2;
    rq[tid] = v0 * v0 + v1 * v1 + v2 * v2;
    __syncthreads();
    for (int st = 128; st > 0; st >>= 1) {
        if (tid < st) { rs[tid] += rs[tid + st]; rq[tid] += rq[tid + st]; }
        __syncthreads();
    }
    float mean = rs[0] * (1.0f / DD);
    float var  = rq[0] * (1.0f / DD) - mean * mean;
    float inv  = rsqrtf(var + 1e-5f);
    uint32_t* o = (uint32_t*)(out + (size_t)row * DD);
    o[tid]       = f2tf((v0 - mean) * inv * sc[tid]       + bi[tid]);
    o[tid + 256] = f2tf((v1 - mean) * inv * sc[tid + 256] + bi[tid + 256]);
    o[tid + 512] = f2tf((v2 - mean) * inv * sc[tid + 512] + bi[tid + 512]);
}

// ---------------- tf32 GEMM: cp.async double-buffered, inputs pre-converted ------
// C[M,N] = A[M,K] @ B[K,N] + bias (+relu)(+res)(+tf32-out).  BM=128, BN=128, BK=32.
// A and B already hold tf32 bit patterns -> inner loop is pure LDS+MMA.
#define TG_ASTR 36
#define TG_BSTR 136
#define TG_ABUF (128 * TG_ASTR)            // 4608 words
#define TG_BBUF (32 * TG_BSTR)             // 4352 words
#define TG_BUF  (TG_ABUF + TG_BBUF)        // 8960 words
#define TG_SMEM (2 * TG_BUF * 4)           // 71680 bytes

template <bool RELU, bool RES, bool CVT>
__global__ __launch_bounds__(256, 2) void tgemm2(
    const float* __restrict__ A, const float* __restrict__ B,
    const float* __restrict__ bias, const float* __restrict__ res,
    float* __restrict__ C, int K, int N)
{
    constexpr int BK = 32;
    extern __shared__ float sm[];
    const uint32_t sbase = (uint32_t)__cvta_generic_to_shared(sm);

    const int tid = threadIdx.x;
    const int bm = blockIdx.y * 128;
    const int bn = blockIdx.x * 128;
    const int wid = tid >> 5, lane = tid & 31;
    const int gid = lane >> 2, tig = lane & 3;
    const int wn = (wid & 3) * 32;
    const int wm = (wid >> 2) * 64;

    const float* Ab = A + (size_t)bm * K;

    float acc[4][4][4];
#pragma unroll
    for (int mi = 0; mi < 4; mi++)
#pragma unroll
        for (int ni = 0; ni < 4; ni++)
#pragma unroll
            for (int q = 0; q < 4; q++) acc[mi][ni][q] = 0.f;

    auto issue = [&](int kt, int p) {
        int k0 = kt * BK;
#pragma unroll
        for (int i = 0; i < 4; i++) {
            int f = i * 256 + tid;
            int r = f >> 3, kq = f & 7;
            uint32_t d = sbase + (uint32_t)(p * TG_BUF + r * TG_ASTR + kq * 4) * 4;
            CP_ASYNC16(d, Ab + (size_t)r * K + k0 + kq * 4);
        }
#pragma unroll
        for (int i = 0; i < 4; i++) {
            int f = i * 256 + tid;
            int kr = f >> 5, nq = f & 31;
            uint32_t d = sbase + (uint32_t)(p * TG_BUF + TG_ABUF + kr * TG_BSTR + nq * 4) * 4;
            CP_ASYNC16(d, B + (size_t)(k0 + kr) * N + bn + nq * 4);
        }
        CP_COMMIT();
    };

    issue(0, 0);

    const int KT = K / BK;
    for (int kt = 0; kt < KT; kt++) {
        const int p = kt & 1;
        if (kt + 1 < KT) { issue(kt + 1, p ^ 1); CP_WAIT(1); }
        else             { CP_WAIT(0); }
        __syncthreads();

        const uint32_t* As = (const uint32_t*)(sm + p * TG_BUF);
        const uint32_t* Bs = As + TG_ABUF;
#pragma unroll
        for (int ks = 0; ks < BK; ks += 8) {
            uint32_t af[4][4], bf[4][2];
#pragma unroll
            for (int mi = 0; mi < 4; mi++) {
                int m = wm + mi * 16 + gid;
                af[mi][0] = As[m * TG_ASTR + ks + tig];
                af[mi][1] = As[(m + 8) * TG_ASTR + ks + tig];
                af[mi][2] = As[m * TG_ASTR + ks + tig + 4];
                af[mi][3] = As[(m + 8) * TG_ASTR + ks + tig + 4];
            }
#pragma unroll
            for (int ni = 0; ni < 4; ni++) {
                int n = wn + ni * 8 + gid;
                bf[ni][0] = Bs[(ks + tig) * TG_BSTR + n];
                bf[ni][1] = Bs[(ks + tig + 4) * TG_BSTR + n];
            }
#pragma unroll
            for (int mi = 0; mi < 4; mi++)
#pragma unroll
                for (int ni = 0; ni < 4; ni++)
                    MMA_TF32(acc[mi][ni], af[mi], bf[ni]);
        }
        __syncthreads();
    }

    // ---- epilogue ----
#pragma unroll
    for (int mi = 0; mi < 4; mi++) {
        int r0 = bm + wm + mi * 16 + gid;
#pragma unroll
        for (int ni = 0; ni < 4; ni++) {
            int c = bn + wn + ni * 8 + tig * 2;
            float b0 = bias[c], b1 = bias[c + 1];
            float v0 = acc[mi][ni][0] + b0;
            float v1 = acc[mi][ni][1] + b1;
            float v2 = acc[mi][ni][2] + b0;
            float v3 = acc[mi][ni][3] + b1;
            if (RELU) {
                v0 = fmaxf(v0, 0.f); v1 = fmaxf(v1, 0.f);
                v2 = fmaxf(v2, 0.f); v3 = fmaxf(v3, 0.f);
            }
            if (RES) {
                const float* rp0 = res + (size_t)r0 * N + c;
                const float* rp1 = res + (size_t)(r0 + 8) * N + c;
                v0 += rp0[0]; v1 += rp0[1];
                v2 += rp1[0]; v3 += rp1[1];
            }
            if (CVT) {
                uint2 w0 = { f2tf(v0), f2tf(v1) };
                uint2 w1 = { f2tf(v2), f2tf(v3) };
                *(uint2*)(C + (size_t)r0 * N + c) = w0;
                *(uint2*)(C + (size_t)(r0 + 8) * N + c) = w1;
            } else {
                float2 w0 = { v0, v1 };
                float2 w1 = { v2, v3 };
                *(float2*)(C + (size_t)r0 * N + c) = w0;
                *(float2*)(C + (size_t)(r0 + 8) * N + c) = w1;
            }
        }
    }
}

// ---------------- fused flash attention ------------------------------------------
// One CTA per (128 q-rows, b, h). qkv already holds tf32 bits -> no CVT on Q/K/V.
// Smem words: Ps 8704 | KV 2x9216 | msk 1024.
#define FA_PS    0
#define FA_KV    8704
#define FA_KVBUF 9216                       // one K+V pair (words)
#define FA_MSK   (FA_KV + 2 * FA_KVBUF)     // 27136
#define FA_WORDS (FA_MSK + 1024)            // 28160
#define FA_SMEM  (FA_WORDS * 4)             // 112640 bytes

__global__ __launch_bounds__(256, 2) void fattn_kernel(
    const float* __restrict__ qkv, const int* __restrict__ mask,
    float* __restrict__ att)
{
    extern __shared__ float sm[];
    const uint32_t sbase = (uint32_t)__cvta_generic_to_shared(sm);
    uint32_t (*Ps)[68] = (uint32_t(*)[68])sm;
    int* msk = (int*)(sm + FA_MSK);

    const int bh = blockIdx.y, b = bh / HH, h = bh % HH;
    const int s0 = blockIdx.x * 128;
    const int tid = threadIdx.x, wid = tid >> 5, lane = tid & 31;
    const int gid = lane >> 2, tig = lane & 3;

    const float* Qg = qkv + (size_t)(b * SS + s0) * TD + h * 192;
    const float* Kg = qkv + (size_t)b * SS * TD + h * 192 + 64;
    const float* Vg = Kg + 64;

    // K/V cp.async mapping: 64 rows x 16 float4; 4 threads/row, 4 float4 each
    const int pr = tid >> 2;
    const int pc = (tid & 3) * 4;

    auto issueKV = [&](int tc, int p) {
        int t0 = tc * 64;
        const float* kp = Kg + (size_t)(t0 + pr) * TD;
        const float* vp = Vg + (size_t)(t0 + pr) * TD;
        uint32_t kd = sbase + (uint32_t)(FA_KV + p * FA_KVBUF + pr * 72) * 4;
        uint32_t vd = kd + 4608 * 4;
#pragma unroll
        for (int i = 0; i < 4; i++) {
            CP_ASYNC16(kd + (pc + i) * 16, kp + (pc + i) * 4);
            CP_ASYNC16(vd + (pc + i) * 16, vp + (pc + i) * 4);
        }
        CP_COMMIT();
    };

    issueKV(0, 0);

    // ---- preload mask row (1024 ints) ----
    ((int4*)msk)[tid] = ((const int4*)(mask + b * SS))[tid];

    // ---- stage Q (128x64, already tf32 bits) via Ps into A-fragments ----
    {
        int r = tid >> 1;
        int c0 = (tid & 1) * 8;
        const uint4* qr = (const uint4*)(Qg + (size_t)r * TD);
#pragma unroll
        for (int i = 0; i < 8; i++)
            *(uint4*)(&Ps[r][(c0 + i) * 4]) = qr[c0 + i];
    }
    __syncthreads();
    uint32_t qf[8][4];
    {
        int m = wid * 16 + gid;
#pragma unroll
        for (int kt = 0; kt < 8; kt++) {
            qf[kt][0] = Ps[m][kt * 8 + tig];
            qf[kt][1] = Ps[m + 8][kt * 8 + tig];
            qf[kt][2] = Ps[m][kt * 8 + tig + 4];
            qf[kt][3] = Ps[m + 8][kt * 8 + tig + 4];
        }
    }
    __syncthreads();   // Q frags loaded before Ps reused for P

    float of[8][4];
#pragma unroll
    for (int ni = 0; ni < 8; ni++)
#pragma unroll
        for (int q = 0; q < 4; q++) of[ni][q] = 0.f;
    float mrun0 = -INFINITY, mrun1 = -INFINITY;
    float lrun0 = 0.f, lrun1 = 0.f;

    for (int tc = 0; tc < SS / 64; tc++) {
        const int p = tc & 1;
        if (tc + 1 < SS / 64) { issueKV(tc + 1, p ^ 1); CP_WAIT(1); }
        else                  { CP_WAIT(0); }
        __syncthreads();

        const uint32_t (*Kf)[72] = (const uint32_t(*)[72])(sm + FA_KV + p * FA_KVBUF);
        const uint32_t (*Vf)[72] = Kf + 64;
        const int* mt = msk + tc * 64;

        // ---- S = Q @ K^T ----
        float sf[8][4];
#pragma unroll
        for (int ni = 0; ni < 8; ni++)
#pragma unroll
            for (int q = 0; q < 4; q++) sf[ni][q] = 0.f;
#pragma unroll
        for (int kt = 0; kt < 8; kt++) {
#pragma unroll
            for (int ni = 0; ni < 8; ni++) {
                uint32_t bf[2];
                bf[0] = Kf[ni * 8 + gid][kt * 8 + tig];
                bf[1] = Kf[ni * 8 + gid][kt * 8 + tig + 4];
                MMA_TF32(sf[ni], qf[kt], bf);
            }
        }

        // ---- mask + scale + online softmax ----
        float mnew0 = mrun0, mnew1 = mrun1;
#pragma unroll
        for (int ni = 0; ni < 8; ni++) {
            int c = ni * 8 + 2 * tig;
            bool m0 = mt[c] == 1, m1 = mt[c + 1] == 1;
            sf[ni][0] = m0 ? -1e9f : sf[ni][0] * 0.125f;
            sf[ni][1] = m1 ? -1e9f : sf[ni][1] * 0.125f;
            sf[ni][2] = m0 ? -1e9f : sf[ni][2] * 0.125f;
            sf[ni][3] = m1 ? -1e9f : sf[ni][3] * 0.125f;
            mnew0 = fmaxf(mnew0, fmaxf(sf[ni][0], sf[ni][1]));
            mnew1 = fmaxf(mnew1, fmaxf(sf[ni][2], sf[ni][3]));
        }
        mnew0 = fmaxf(mnew0, __shfl_xor_sync(0xffffffffu, mnew0, 1));
        mnew0 = fmaxf(mnew0, __shfl_xor_sync(0xffffffffu, mnew0, 2));
        mnew1 = fmaxf(mnew1, __shfl_xor_sync(0xffffffffu, mnew1, 1));
        mnew1 = fmaxf(mnew1, __shfl_xor_sync(0xffffffffu, mnew1, 2));
        float alpha0 = __expf(mrun0 - mnew0);
        float alpha1 = __expf(mrun1 - mnew1);
        mrun0 = mnew0; mrun1 = mnew1;

        float rs0 = 0.f, rs1 = 0.f;
#pragma unroll
        for (int ni = 0; ni < 8; ni++) {
            sf[ni][0] = __expf(sf[ni][0] - mnew0);
            sf[ni][1] = __expf(sf[ni][1] - mnew0);
            sf[ni][2] = __expf(sf[ni][2] - mnew1);
            sf[ni][3] = __expf(sf[ni][3] - mnew1);
            rs0 += sf[ni][0] + sf[ni][1];
            rs1 += sf[ni][2] + sf[ni][3];
        }
        rs0 += __shfl_xor_sync(0xffffffffu, rs0, 1);
        rs0 += __shfl_xor_sync(0xffffffffu, rs0, 2);
        rs1 += __shfl_xor_sync(0xffffffffu, rs1, 1);
        rs1 += __shfl_xor_sync(0xffffffffu, rs1, 2);
        lrun0 = lrun0 * alpha0 + rs0;
        lrun1 = lrun1 * alpha1 + rs1;
#pragma unroll
        for (int ni = 0; ni < 8; ni++) {
            of[ni][0] *= alpha0; of[ni][1] *= alpha0;
            of[ni][2] *= alpha1; of[ni][3] *= alpha1;
        }

        // ---- write P (tf32) to own rows of Ps ----
        {
            int r0 = wid * 16 + gid;
#pragma unroll
            for (int ni = 0; ni < 8; ni++) {
                int c = ni * 8 + 2 * tig;
                uint2 u0 = { f2tf(sf[ni][0]), f2tf(sf[ni][1]) };
                *(uint2*)(&Ps[r0][c]) = u0;
                uint2 u1 = { f2tf(sf[ni][2]), f2tf(sf[ni][3]) };
                *(uint2*)(&Ps[r0 + 8][c]) = u1;
            }
        }

        // ---- O += P @ V (reads only this warp's P rows) ----
        {
            int m = wid * 16 + gid;
#pragma unroll
            for (int kt = 0; kt < 8; kt++) {
                uint32_t a[4];
                a[0] = Ps[m][kt * 8 + tig];
                a[1] = Ps[m + 8][kt * 8 + tig];
                a[2] = Ps[m][kt * 8 + tig + 4];
                a[3] = Ps[m + 8][kt * 8 + tig + 4];
#pragma unroll
                for (int ni = 0; ni < 8; ni++) {
                    uint32_t bf[2];
                    bf[0] = Vf[kt * 8 + tig][ni * 8 + gid];
                    bf[1] = Vf[kt * 8 + tig + 4][ni * 8 + gid];
                    MMA_TF32(of[ni], a, bf);
                }
            }
        }
        __syncthreads();   // all reads of this K/V buffer done before overwrite
    }

    // ---- epilogue: O /= l, write tf32 bits to att (consumed as GEMM A) ----
    float inv0 = 1.f / lrun0;
    float inv1 = 1.f / lrun1;
    int r0 = s0 + wid * 16 + gid;
#pragma unroll
    for (int ni = 0; ni < 8; ni++) {
        int c = h * 64 + ni * 8 + 2 * tig;
        uint2 v0 = { f2tf(of[ni][0] * inv0), f2tf(of[ni][1] * inv0) };
        *(uint2*)(att + (size_t)(b * SS + r0) * DD + c) = v0;
        uint2 v1 = { f2tf(of[ni][2] * inv1), f2tf(of[ni][3] * inv1) };
        *(uint2*)(att + (size_t)(b * SS + r0 + 8) * DD + c) = v1;
    }
}

// ---------------- final head: LN(x[:,0,:]) @ cls_w + cls_b ------------------------
__global__ __launch_bounds__(256) void head_kernel(const float* __restrict__ x,
                                                   const float* __restrict__ hs,
                                                   const float* __restrict__ hb,
                                                   const float* __restrict__ cw,
                                                   const float* __restrict__ cb,
                                                   float* __restrict__ out) {
    int b = blockIdx.x;
    int tid = threadIdx.x;
    const float* p = x + (size_t)b * SS * DD;   // s = 0 row
    float v0 = p[tid], v1 = p[tid + 256], v2 = p[tid + 512];
    __shared__ float rs[256], rq[256];
    rs[tid] = v0 + v1 + v2;
    rq[tid] = v0 * v0 + v1 * v1 + v2 * v2;
    __syncthreads();
    for (int st = 128; st > 0; st >>= 1) {
        if (tid < st) { rs[tid] += rs[tid + st]; rq[tid] += rq[tid + st]; }
        __syncthreads();
    }
    float mean = rs[0] * (1.0f / DD);
    float var  = rq[0] * (1.0f / DD) - mean * mean;
    float inv  = rsqrtf(var + 1e-5f);
    float p0 = (v0 - mean) * inv * hs[tid]       + hb[tid];
    float p1 = (v1 - mean) * inv * hs[tid + 256] + hb[tid + 256];
    float p2 = (v2 - mean) * inv * hs[tid + 512] + hb[tid + 512];
    float d0 = p0 * cw[2 * tid]     + p1 * cw[2 * (tid + 256)]     + p2 * cw[2 * (tid + 512)];
    float d1 = p0 * cw[2 * tid + 1] + p1 * cw[2 * (tid + 256) + 1] + p2 * cw[2 * (tid + 512) + 1];
    __syncthreads();
    rs[tid] = d0; rq[tid] = d1;
    __syncthreads();
    for (int st = 128; st > 0; st >>= 1) {
        if (tid < st) { rs[tid] += rs[tid + st]; rq[tid] += rq[tid + st]; }
        __syncthreads();
    }
    if (tid == 0) {
        out[2 * b]     = rs[0] + cb[0];
        out[2 * b + 1] = rq[0] + cb[1];
    }
}

// ---------------- host orchestration ---------------------------------------------
extern "C" void kernel_launch(void* const* d_in, const int* in_sizes, int n_in,
                              void* d_out, int out_size) {
    const int*   input_ids = (const int*)d_in[0];
    const int*   attn_mask = (const int*)d_in[1];
    const float* token_emb = (const float*)d_in[2];
    const float* pos_emb   = (const float*)d_in[3];
    const float* qkv_w     = (const float*)d_in[4];
    const float* qkv_b     = (const float*)d_in[5];
    const float* out_w     = (const float*)d_in[6];
    const float* out_b     = (const float*)d_in[7];
    const float* n1_s      = (const float*)d_in[8];
    const float* n1_b      = (const float*)d_in[9];
    const float* ff1_w     = (const float*)d_in[10];
    const float* ff1_b     = (const float*)d_in[11];
    const float* ff2_w     = (const float*)d_in[12];
    const float* ff2_b     = (const float*)d_in[13];
    const float* n2_s      = (const float*)d_in[14];
    const float* n2_b      = (const float*)d_in[15];
    const float* hln_s     = (const float*)d_in[16];
    const float* hln_b     = (const float*)d_in[17];
    const float* cls_w     = (const float*)d_in[18];
    const float* cls_b     = (const float*)d_in[19];
    float* out = (float*)d_out;

    float *x, *h, *qkv, *att, *ff, *wt;
    cudaGetSymbolAddress((void**)&x,   g_x);
    cudaGetSymbolAddress((void**)&h,   g_h);
    cudaGetSymbolAddress((void**)&qkv, g_qkv);
    cudaGetSymbolAddress((void**)&att, g_att);
    cudaGetSymbolAddress((void**)&ff,  g_ff);
    cudaGetSymbolAddress((void**)&wt,  g_wt);

    cudaFuncSetAttribute(fattn_kernel,
                         cudaFuncAttributeMaxDynamicSharedMemorySize, FA_SMEM);
    cudaFuncSetAttribute(tgemm2<false, false, true>,
                         cudaFuncAttributeMaxDynamicSharedMemorySize, TG_SMEM);
    cudaFuncSetAttribute(tgemm2<false, true, false>,
                         cudaFuncAttributeMaxDynamicSharedMemorySize, TG_SMEM);
    cudaFuncSetAttribute(tgemm2<true, false, true>,
                         cudaFuncAttributeMaxDynamicSharedMemorySize, TG_SMEM);

    // ---- convert all weights to tf32 bit patterns (once per launch) ----
    {
        int n;
        n = LL * DD * TD / 4;
        cvtw_kernel<<<(n + 255) / 256, 256>>>(qkv_w, wt + W_QKV, n);
        n = LL * DD * DD / 4;
        cvtw_kernel<<<(n + 255) / 256, 256>>>(out_w, wt + W_OUT, n);
        n = LL * DD * DF / 4;
        cvtw_kernel<<<(n + 255) / 256, 256>>>(ff1_w, wt + W_FF1, n);
        n = LL * DF * DD / 4;
        cvtw_kernel<<<(n + 255) / 256, 256>>>(ff2_w, wt + W_FF2, n);
    }

    embed_kernel<<<(NROWS * DD + 255) / 256, 256>>>(input_ids, token_emb, pos_emb, x);

    for (int i = 0; i < LL; i++) {
        ln_kernel<<<NROWS, 256>>>(x, n1_s + i * DD, n1_b + i * DD, h);
        // QKV projection: [8192,768] @ [768,2304] -> tf32-bit output
        tgemm2<false, false, true><<<dim3(TD / 128, NROWS / 128), 256, TG_SMEM>>>(
            h, wt + W_QKV + (size_t)i * DD * TD, qkv_b + i * TD, nullptr, qkv, DD, TD);
        // fused attention: scores + softmax + P@V, no DRAM score tensor
        fattn_kernel<<<dim3(SS / 128, BB * HH), 256, FA_SMEM>>>(qkv, attn_mask, att);
        // out projection + residual (fp32 output)
        tgemm2<false, true, false><<<dim3(DD / 128, NROWS / 128), 256, TG_SMEM>>>(
            att, wt + W_OUT + (size_t)i * DD * DD, out_b + i * DD, x, x, DD, DD);
        ln_kernel<<<NROWS, 256>>>(x, n2_s + i * DD, n2_b + i * DD, h);
        // FF1 + relu -> tf32-bit output
        tgemm2<true, false, true><<<dim3(DF / 128, NROWS / 128), 256, TG_SMEM>>>(
            h, wt + W_FF1 + (size_t)i * DD * DF, ff1_b + i * DF, nullptr, ff, DD, DF);
        // FF2 + residual (fp32 output)
        tgemm2<false, true, false><<<dim3(DD / 128, NROWS / 128), 256, TG_SMEM>>>(
            ff, wt + W_FF2 + (size_t)i * DF * DD, ff2_b + i * DD, x, x, DF, DD);
    }

    head_kernel<<<BB, 256>>>(x, hln_s, hln_b, cls_w, cls_b, out);
}

// round 12
// speedup vs baseline: 2.4781x; 1.9954x over previous
#include <cuda_runtime.h>
#include <cuda_fp16.h>
#include <cstdint>

// Problem constants
#define BB 8
#define SS 1024
#define DD 768
#define HH 12
#define LL 6
#define DF 3072
#define HD 64
#define TD 2304   // 3*D
#define NROWS (BB*SS)   // 8192

// ---------------- scratch (static device globals; no allocs allowed) -------------
__device__ float  g_x[NROWS * DD];                // residual stream (fp32)
__device__ __half g_h[NROWS * DD];                // layernorm output (half)
__device__ __half g_qkv[NROWS * TD];              // qkv projection (half)
__device__ __half g_att[NROWS * DD];              // attention output (half)
__device__ __half g_ff[NROWS * DF];               // ff1 output (half)

// converted (half) weights
#define W_QKV 0
#define W_OUT (LL * DD * TD)
#define W_FF1 (W_OUT + LL * DD * DD)
#define W_FF2 (W_FF1 + LL * DD * DF)
#define W_TOT (W_FF2 + LL * DF * DD)
__device__ __half g_wt[W_TOT];

// ---------------- asm helpers ----------------------------------------------------
#define MMA_F16(c, a, b)                                                         \
    asm volatile(                                                                \
        "mma.sync.aligned.m16n8k16.row.col.f32.f16.f16.f32 "                     \
        "{%0,%1,%2,%3},{%4,%5,%6,%7},{%8,%9},{%0,%1,%2,%3};"                     \
        : "+f"((c)[0]), "+f"((c)[1]), "+f"((c)[2]), "+f"((c)[3])                 \
        : "r"((a)[0]), "r"((a)[1]), "r"((a)[2]), "r"((a)[3]),                    \
          "r"((b)[0]), "r"((b)[1]))

#define LDSM4(r0, r1, r2, r3, addr)                                              \
    asm volatile("ldmatrix.sync.aligned.m8n8.x4.shared.b16 {%0,%1,%2,%3},[%4];"  \
        : "=r"(r0), "=r"(r1), "=r"(r2), "=r"(r3) : "r"(addr))

#define LDSM4T(r0, r1, r2, r3, addr)                                             \
    asm volatile("ldmatrix.sync.aligned.m8n8.x4.trans.shared.b16 {%0,%1,%2,%3},[%4];" \
        : "=r"(r0), "=r"(r1), "=r"(r2), "=r"(r3) : "r"(addr))

#define CP_ASYNC16(dst, src)                                                     \
    asm volatile("cp.async.cg.shared.global [%0], [%1], 16;" :: "r"(dst), "l"(src))
#define CP_COMMIT() asm volatile("cp.async.commit_group;")
#define CP_WAIT(n)  asm volatile("cp.async.wait_group %0;" :: "n"(n))

__device__ __forceinline__ uint32_t packh2(float a, float b) {
    __half2 h = __floats2half2_rn(a, b);
    return *(uint32_t*)&h;
}

// ---------------- weight conversion (fp32 -> half), vectorized -------------------
__global__ __launch_bounds__(256) void cvtw_kernel(const float* __restrict__ in,
                                                   __half* __restrict__ out, int n8) {
    int i = blockIdx.x * blockDim.x + threadIdx.x;
    if (i >= n8) return;
    const float4* p = (const float4*)in;
    float4 v0 = p[2 * i], v1 = p[2 * i + 1];
    uint4 u;
    u.x = packh2(v0.x, v0.y);
    u.y = packh2(v0.z, v0.w);
    u.z = packh2(v1.x, v1.y);
    u.w = packh2(v1.z, v1.w);
    ((uint4*)out)[i] = u;
}

// ---------------- embedding ------------------------------------------------------
__global__ void embed_kernel(const int* __restrict__ ids,
                             const float* __restrict__ tok,
                             const float* __restrict__ pos,
                             float* __restrict__ x) {
    int idx = blockIdx.x * blockDim.x + threadIdx.x;
    if (idx >= NROWS * DD) return;
    int bs = idx / DD;
    int d  = idx - bs * DD;
    int s  = bs & (SS - 1);
    x[idx] = (tok[(size_t)ids[bs] * DD + d] + pos[s * DD + d]) * 27.712812921102035f;
}

// ---------------- layernorm: fp32 in, half out ------------------------------------
__global__ __launch_bounds__(256) void ln_kernel(const float* __restrict__ x,
                                                 const float* __restrict__ sc,
                                                 const float* __restrict__ bi,
                                                 __half* __restrict__ out) {
    int row = blockIdx.x;
    int tid = threadIdx.x;
    const float* p = x + (size_t)row * DD;
    float v0 = p[tid], v1 = p[tid + 256], v2 = p[tid + 512];
    __shared__ float rs[256], rq[256];
    rs[tid] = v0 + v1 + v2;
    rq[tid] = v0 * v0 + v1 * v1 + v2 * v2;
    __syncthreads();
    for (int st = 128; st > 0; st >>= 1) {
        if (tid < st) { rs[tid] += rs[tid + st]; rq[tid] += rq[tid + st]; }
        __syncthreads();
    }
    float mean = rs[0] * (1.0f / DD);
    float var  = rq[0] * (1.0f / DD) - mean * mean;
    float inv  = rsqrtf(var + 1e-5f);
    __half* o = out + (size_t)row * DD;
    o[tid]       = __float2half((v0 - mean) * inv * sc[tid]       + bi[tid]);
    o[tid + 256] = __float2half((v1 - mean) * inv * sc[tid + 256] + bi[tid + 256]);
    o[tid + 512] = __float2half((v2 - mean) * inv * sc[tid + 512] + bi[tid + 512]);
}

// ---------------- fp16 GEMM: cp.async double-buffered + ldmatrix -----------------
// C[M,N] = A[M,K] @ B[K,N] + bias (+relu)(+res).  BM=128, BN=128, BK=32.
// A stride 40 halfs (80B), B stride 136 halfs (272B) -> conflict-free ldmatrix.
#define TG_ABYTES (128 * 40 * 2)           // 10240
#define TG_BBYTES (32 * 136 * 2)           // 8704
#define TG_BUFB   (TG_ABYTES + TG_BBYTES)  // 18944
#define TG_SMEM   (2 * TG_BUFB)            // 37888

template <bool RELU, bool RES, bool CVT>
__global__ __launch_bounds__(256, 2) void hgemm(
    const __half* __restrict__ A, const __half* __restrict__ B,
    const float* __restrict__ bias, const float* __restrict__ res,
    void* __restrict__ Cv, int K, int N)
{
    extern __shared__ char smc[];
    const uint32_t sbase = (uint32_t)__cvta_generic_to_shared(smc);

    const int tid = threadIdx.x;
    const int bm = blockIdx.y * 128;
    const int bn = blockIdx.x * 128;
    const int wid = tid >> 5, lane = tid & 31;
    const int gid = lane >> 2, tig = lane & 3;
    const int wn = (wid & 3) * 32;
    const int wm = (wid >> 2) * 64;

    const __half* Ab = A + (size_t)bm * K;

    float acc[4][4][4];
#pragma unroll
    for (int mi = 0; mi < 4; mi++)
#pragma unroll
        for (int ni = 0; ni < 4; ni++)
#pragma unroll
            for (int q = 0; q < 4; q++) acc[mi][ni][q] = 0.f;

    auto issue = [&](int kt, int p) {
        int k0 = kt * 32;
#pragma unroll
        for (int i = 0; i < 2; i++) {
            int f = i * 256 + tid;
            int r = f >> 2, cq = f & 3;            // A: 128 rows x 4 chunks
            uint32_t d = sbase + p * TG_BUFB + r * 80 + cq * 16;
            CP_ASYNC16(d, Ab + (size_t)r * K + k0 + cq * 8);
        }
#pragma unroll
        for (int i = 0; i < 2; i++) {
            int f = i * 256 + tid;
            int kr = f >> 4, nq = f & 15;          // B: 32 rows x 16 chunks
            uint32_t d = sbase + p * TG_BUFB + TG_ABYTES + kr * 272 + nq * 16;
            CP_ASYNC16(d, B + (size_t)(k0 + kr) * N + bn + nq * 8);
        }
        CP_COMMIT();
    };

    issue(0, 0);

    // ldmatrix lane-derived offsets
    const int arow = lane & 15;                    // A row within 16-block
    const int acol = (lane >> 4) << 3;             // A col +0/+8
    const int brow = (lane & 7) + ((lane & 8) ? 8 : 0);   // B k row
    const int bcol = (lane & 16) ? 8 : 0;          // B n +0/+8

    const int KT = K / 32;
    for (int kt = 0; kt < KT; kt++) {
        const int p = kt & 1;
        if (kt + 1 < KT) { issue(kt + 1, p ^ 1); CP_WAIT(1); }
        else             { CP_WAIT(0); }
        __syncthreads();

        const uint32_t abase = sbase + p * TG_BUFB;
        const uint32_t bbase = abase + TG_ABYTES;
#pragma unroll
        for (int ks = 0; ks < 32; ks += 16) {
            uint32_t af[4][4], bf[4][2];
#pragma unroll
            for (int mi = 0; mi < 4; mi++) {
                uint32_t ad = abase + (wm + mi * 16 + arow) * 80 + (ks + acol) * 2;
                LDSM4(af[mi][0], af[mi][1], af[mi][2], af[mi][3], ad);
            }
#pragma unroll
            for (int hn = 0; hn < 2; hn++) {
                uint32_t bd = bbase + (ks + brow) * 272 + (wn + hn * 16 + bcol) * 2;
                LDSM4T(bf[2 * hn][0], bf[2 * hn][1], bf[2 * hn + 1][0], bf[2 * hn + 1][1], bd);
            }
#pragma unroll
            for (int mi = 0; mi < 4; mi++)
#pragma unroll
                for (int ni = 0; ni < 4; ni++)
                    MMA_F16(acc[mi][ni], af[mi], bf[ni]);
        }
        __syncthreads();
    }

    // ---- epilogue ----
#pragma unroll
    for (int mi = 0; mi < 4; mi++) {
        int r0 = bm + wm + mi * 16 + gid;
#pragma unroll
        for (int ni = 0; ni < 4; ni++) {
            int c = bn + wn + ni * 8 + tig * 2;
            float b0 = bias[c], b1 = bias[c + 1];
            float v0 = acc[mi][ni][0] + b0;
            float v1 = acc[mi][ni][1] + b1;
            float v2 = acc[mi][ni][2] + b0;
            float v3 = acc[mi][ni][3] + b1;
            if (RELU) {
                v0 = fmaxf(v0, 0.f); v1 = fmaxf(v1, 0.f);
                v2 = fmaxf(v2, 0.f); v3 = fmaxf(v3, 0.f);
            }
            if (RES) {
                const float* rp0 = res + (size_t)r0 * N + c;
                const float* rp1 = res + (size_t)(r0 + 8) * N + c;
                v0 += rp0[0]; v1 += rp0[1];
                v2 += rp1[0]; v3 += rp1[1];
            }
            if (CVT) {
                __half* C = (__half*)Cv;
                *(uint32_t*)(C + (size_t)r0 * N + c)       = packh2(v0, v1);
                *(uint32_t*)(C + (size_t)(r0 + 8) * N + c) = packh2(v2, v3);
            } else {
                float* C = (float*)Cv;
                float2 w0 = { v0, v1 };
                float2 w1 = { v2, v3 };
                *(float2*)(C + (size_t)r0 * N + c) = w0;
                *(float2*)(C + (size_t)(r0 + 8) * N + c) = w1;
            }
        }
    }
}

// ---------------- fused flash attention (fp16 MMA) --------------------------------
// One CTA per (128 q-rows, b, h). P stays in registers (fp16 frag layout == S C
// layout). Smem bytes: Qs 18432 | K/V 2x18432 | msk 4096 = 59392.
#define FA_QS    0
#define FA_KV0   18432
#define FA_KVP   18432                      // one K+V pair
#define FA_MSKB  (FA_KV0 + 2 * FA_KVP)      // 55296
#define FA_SMEM  (FA_MSKB + 4096)           // 59392

__global__ __launch_bounds__(256, 2) void fattn_kernel(
    const __half* __restrict__ qkv, const int* __restrict__ mask,
    __half* __restrict__ att)
{
    extern __shared__ char smc[];
    const uint32_t sbase = (uint32_t)__cvta_generic_to_shared(smc);
    int* msk = (int*)(smc + FA_MSKB);

    const int bh = blockIdx.y, b = bh / HH, h = bh % HH;
    const int s0 = blockIdx.x * 128;
    const int tid = threadIdx.x, wid = tid >> 5, lane = tid & 31;
    const int gid = lane >> 2, tig = lane & 3;

    const __half* Qg = qkv + (size_t)(b * SS + s0) * TD + h * 192;
    const __half* Kg = qkv + (size_t)b * SS * TD + h * 192 + 64;
    const __half* Vg = Kg + 64;

    // ---- issue Q (group A) then KV0 (group B) ----
    {
#pragma unroll
        for (int i = 0; i < 4; i++) {                 // Q: 128 rows x 8 chunks
            int f = i * 256 + tid;
            int r = f >> 3, cq = f & 7;
            uint32_t d = sbase + FA_QS + r * 144 + cq * 16;
            CP_ASYNC16(d, Qg + (size_t)r * TD + cq * 8);
        }
        CP_COMMIT();
    }
    auto issueKV = [&](int tc, int p) {
        int t0 = tc * 64;
#pragma unroll
        for (int i = 0; i < 2; i++) {                 // K: 64 rows x 8 chunks
            int f = i * 256 + tid;
            int r = f >> 3, cq = f & 7;
            uint32_t kd = sbase + FA_KV0 + p * FA_KVP + r * 144 + cq * 16;
            CP_ASYNC16(kd, Kg + (size_t)(t0 + r) * TD + cq * 8);
            uint32_t vd = kd + 9216;
            CP_ASYNC16(vd, Vg + (size_t)(t0 + r) * TD + cq * 8);
        }
        CP_COMMIT();
    };
    issueKV(0, 0);

    // ---- preload mask row (1024 ints) ----
    ((int4*)msk)[tid] = ((const int4*)(mask + b * SS))[tid];

    // ldmatrix lane offsets
    const int arow = lane & 15;
    const int acol = (lane >> 4) << 3;
    const int krow = (lane & 7) + ((lane & 16) ? 8 : 0);   // K: row sel by bit4
    const int kcol = (lane & 8) ? 8 : 0;
    const int vrow = (lane & 7) + ((lane & 8) ? 8 : 0);    // V: row sel by bit3
    const int vcol = (lane & 16) ? 8 : 0;

    // ---- Q fragments (wait group A done: pending <= 1) ----
    CP_WAIT(1);
    __syncthreads();
    uint32_t qf[4][4];
#pragma unroll
    for (int kb = 0; kb < 4; kb++) {
        uint32_t ad = sbase + FA_QS + (wid * 16 + arow) * 144 + (kb * 16 + acol) * 2;
        LDSM4(qf[kb][0], qf[kb][1], qf[kb][2], qf[kb][3], ad);
    }

    float of[8][4];
#pragma unroll
    for (int ni = 0; ni < 8; ni++)
#pragma unroll
        for (int q = 0; q < 4; q++) of[ni][q] = 0.f;
    float mrun0 = -INFINITY, mrun1 = -INFINITY;
    float lrun0 = 0.f, lrun1 = 0.f;

    for (int tc = 0; tc < SS / 64; tc++) {
        const int p = tc & 1;
        if (tc + 1 < SS / 64) { issueKV(tc + 1, p ^ 1); CP_WAIT(1); }
        else                  { CP_WAIT(0); }
        __syncthreads();

        const uint32_t kbase = sbase + FA_KV0 + p * FA_KVP;
        const uint32_t vbase = kbase + 9216;
        const int* mt = msk + tc * 64;

        // ---- S = Q @ K^T ----
        float sf[8][4];
#pragma unroll
        for (int ni = 0; ni < 8; ni++)
#pragma unroll
            for (int q = 0; q < 4; q++) sf[ni][q] = 0.f;
#pragma unroll
        for (int kb = 0; kb < 4; kb++) {
#pragma unroll
            for (int tb2 = 0; tb2 < 4; tb2++) {
                uint32_t r0, r1, r2, r3;
                uint32_t kd = kbase + (tb2 * 16 + krow) * 144 + (kb * 16 + kcol) * 2;
                LDSM4(r0, r1, r2, r3, kd);
                uint32_t bf0[2] = { r0, r1 };
                uint32_t bf1[2] = { r2, r3 };
                MMA_F16(sf[2 * tb2],     qf[kb], bf0);
                MMA_F16(sf[2 * tb2 + 1], qf[kb], bf1);
            }
        }

        // ---- mask + scale + online softmax ----
        float mnew0 = mrun0, mnew1 = mrun1;
#pragma unroll
        for (int ni = 0; ni < 8; ni++) {
            int c = ni * 8 + 2 * tig;
            bool m0 = mt[c] == 1, m1 = mt[c + 1] == 1;
            sf[ni][0] = m0 ? -1e9f : sf[ni][0] * 0.125f;
            sf[ni][1] = m1 ? -1e9f : sf[ni][1] * 0.125f;
            sf[ni][2] = m0 ? -1e9f : sf[ni][2] * 0.125f;
            sf[ni][3] = m1 ? -1e9f : sf[ni][3] * 0.125f;
            mnew0 = fmaxf(mnew0, fmaxf(sf[ni][0], sf[ni][1]));
            mnew1 = fmaxf(mnew1, fmaxf(sf[ni][2], sf[ni][3]));
        }
        mnew0 = fmaxf(mnew0, __shfl_xor_sync(0xffffffffu, mnew0, 1));
        mnew0 = fmaxf(mnew0, __shfl_xor_sync(0xffffffffu, mnew0, 2));
        mnew1 = fmaxf(mnew1, __shfl_xor_sync(0xffffffffu, mnew1, 1));
        mnew1 = fmaxf(mnew1, __shfl_xor_sync(0xffffffffu, mnew1, 2));
        float alpha0 = __expf(mrun0 - mnew0);
        float alpha1 = __expf(mrun1 - mnew1);
        mrun0 = mnew0; mrun1 = mnew1;

        float rs0 = 0.f, rs1 = 0.f;
#pragma unroll
        for (int ni = 0; ni < 8; ni++) {
            sf[ni][0] = __expf(sf[ni][0] - mnew0);
            sf[ni][1] = __expf(sf[ni][1] - mnew0);
            sf[ni][2] = __expf(sf[ni][2] - mnew1);
            sf[ni][3] = __expf(sf[ni][3] - mnew1);
            rs0 += sf[ni][0] + sf[ni][1];
            rs1 += sf[ni][2] + sf[ni][3];
        }
        rs0 += __shfl_xor_sync(0xffffffffu, rs0, 1);
        rs0 += __shfl_xor_sync(0xffffffffu, rs0, 2);
        rs1 += __shfl_xor_sync(0xffffffffu, rs1, 1);
        rs1 += __shfl_xor_sync(0xffffffffu, rs1, 2);
        lrun0 = lrun0 * alpha0 + rs0;
        lrun1 = lrun1 * alpha1 + rs1;
#pragma unroll
        for (int ni = 0; ni < 8; ni++) {
            of[ni][0] *= alpha0; of[ni][1] *= alpha0;
            of[ni][2] *= alpha1; of[ni][3] *= alpha1;
        }

        // ---- O += P @ V : P packed straight from registers (no smem) ----
#pragma unroll
        for (int kb2 = 0; kb2 < 4; kb2++) {
            uint32_t pa[4];
            pa[0] = packh2(sf[2 * kb2][0],     sf[2 * kb2][1]);
            pa[1] = packh2(sf[2 * kb2][2],     sf[2 * kb2][3]);
            pa[2] = packh2(sf[2 * kb2 + 1][0], sf[2 * kb2 + 1][1]);
            pa[3] = packh2(sf[2 * kb2 + 1][2], sf[2 * kb2 + 1][3]);
#pragma unroll
            for (int db2 = 0; db2 < 4; db2++) {
                uint32_t r0, r1, r2, r3;
                uint32_t vd = vbase + (kb2 * 16 + vrow) * 144 + (db2 * 16 + vcol) * 2;
                LDSM4T(r0, r1, r2, r3, vd);
                uint32_t bf0[2] = { r0, r1 };
                uint32_t bf1[2] = { r2, r3 };
                MMA_F16(of[2 * db2],     pa, bf0);
                MMA_F16(of[2 * db2 + 1], pa, bf1);
            }
        }
        __syncthreads();   // all reads of this K/V buffer done before overwrite
    }

    // ---- epilogue: O /= l, write half to att ----
    float inv0 = 1.f / lrun0;
    float inv1 = 1.f / lrun1;
    int r0 = s0 + wid * 16 + gid;
#pragma unroll
    for (int ni = 0; ni < 8; ni++) {
        int c = h * 64 + ni * 8 + 2 * tig;
        *(uint32_t*)(att + (size_t)(b * SS + r0) * DD + c) =
            packh2(of[ni][0] * inv0, of[ni][1] * inv0);
        *(uint32_t*)(att + (size_t)(b * SS + r0 + 8) * DD + c) =
            packh2(of[ni][2] * inv1, of[ni][3] * inv1);
    }
}

// ---------------- final head: LN(x[:,0,:]) @ cls_w + cls_b ------------------------
__global__ __launch_bounds__(256) void head_kernel(const float* __restrict__ x,
                                                   const float* __restrict__ hs,
                                                   const float* __restrict__ hb,
                                                   const float* __restrict__ cw,
                                                   const float* __restrict__ cb,
                                                   float* __restrict__ out) {
    int b = blockIdx.x;
    int tid = threadIdx.x;
    const float* p = x + (size_t)b * SS * DD;   // s = 0 row
    float v0 = p[tid], v1 = p[tid + 256], v2 = p[tid + 512];
    __shared__ float rs[256], rq[256];
    rs[tid] = v0 + v1 + v2;
    rq[tid] = v0 * v0 + v1 * v1 + v2 * v2;
    __syncthreads();
    for (int st = 128; st > 0; st >>= 1) {
        if (tid < st) { rs[tid] += rs[tid + st]; rq[tid] += rq[tid + st]; }
        __syncthreads();
    }
    float mean = rs[0] * (1.0f / DD);
    float var  = rq[0] * (1.0f / DD) - mean * mean;
    float inv  = rsqrtf(var + 1e-5f);
    float p0 = (v0 - mean) * inv * hs[tid]       + hb[tid];
    float p1 = (v1 - mean) * inv * hs[tid + 256] + hb[tid + 256];
    float p2 = (v2 - mean) * inv * hs[tid + 512] + hb[tid + 512];
    float d0 = p0 * cw[2 * tid]     + p1 * cw[2 * (tid + 256)]     + p2 * cw[2 * (tid + 512)];
    float d1 = p0 * cw[2 * tid + 1] + p1 * cw[2 * (tid + 256) + 1] + p2 * cw[2 * (tid + 512) + 1];
    __syncthreads();
    rs[tid] = d0; rq[tid] = d1;
    __syncthreads();
    for (int st = 128; st > 0; st >>= 1) {
        if (tid < st) { rs[tid] += rs[tid + st]; rq[tid] += rq[tid + st]; }
        __syncthreads();
    }
    if (tid == 0) {
        out[2 * b]     = rs[0] + cb[0];
        out[2 * b + 1] = rq[0] + cb[1];
    }
}

// ---------------- host orchestration ---------------------------------------------
extern "C" void kernel_launch(void* const* d_in, const int* in_sizes, int n_in,
                              void* d_out, int out_size) {
    const int*   input_ids = (const int*)d_in[0];
    const int*   attn_mask = (const int*)d_in[1];
    const float* token_emb = (const float*)d_in[2];
    const float* pos_emb   = (const float*)d_in[3];
    const float* qkv_w     = (const float*)d_in[4];
    const float* qkv_b     = (const float*)d_in[5];
    const float* out_w     = (const float*)d_in[6];
    const float* out_b     = (const float*)d_in[7];
    const float* n1_s      = (const float*)d_in[8];
    const float* n1_b      = (const float*)d_in[9];
    const float* ff1_w     = (const float*)d_in[10];
    const float* ff1_b     = (const float*)d_in[11];
    const float* ff2_w     = (const float*)d_in[12];
    const float* ff2_b     = (const float*)d_in[13];
    const float* n2_s      = (const float*)d_in[14];
    const float* n2_b      = (const float*)d_in[15];
    const float* hln_s     = (const float*)d_in[16];
    const float* hln_b     = (const float*)d_in[17];
    const float* cls_w     = (const float*)d_in[18];
    const float* cls_b     = (const float*)d_in[19];
    float* out = (float*)d_out;

    float *x;
    __half *h, *qkv, *att, *ff, *wt;
    cudaGetSymbolAddress((void**)&x,   g_x);
    cudaGetSymbolAddress((void**)&h,   g_h);
    cudaGetSymbolAddress((void**)&qkv, g_qkv);
    cudaGetSymbolAddress((void**)&att, g_att);
    cudaGetSymbolAddress((void**)&ff,  g_ff);
    cudaGetSymbolAddress((void**)&wt,  g_wt);

    cudaFuncSetAttribute(fattn_kernel,
                         cudaFuncAttributeMaxDynamicSharedMemorySize, FA_SMEM);

    // ---- convert all weights to half (once per launch) ----
    {
        int n;
        n = LL * DD * TD / 8;
        cvtw_kernel<<<(n + 255) / 256, 256>>>(qkv_w, wt + W_QKV, n);
        n = LL * DD * DD / 8;
        cvtw_kernel<<<(n + 255) / 256, 256>>>(out_w, wt + W_OUT, n);
        n = LL * DD * DF / 8;
        cvtw_kernel<<<(n + 255) / 256, 256>>>(ff1_w, wt + W_FF1, n);
        n = LL * DF * DD / 8;
        cvtw_kernel<<<(n + 255) / 256, 256>>>(ff2_w, wt + W_FF2, n);
    }

    embed_kernel<<<(NROWS * DD + 255) / 256, 256>>>(input_ids, token_emb, pos_emb, x);

    for (int i = 0; i < LL; i++) {
        ln_kernel<<<NROWS, 256>>>(x, n1_s + i * DD, n1_b + i * DD, h);
        // QKV projection -> half
        hgemm<false, false, true><<<dim3(TD / 128, NROWS / 128), 256, TG_SMEM>>>(
            h, wt + W_QKV + (size_t)i * DD * TD, qkv_b + i * TD, nullptr, qkv, DD, TD);
        // fused attention
        fattn_kernel<<<dim3(SS / 128, BB * HH), 256, FA_SMEM>>>(qkv, attn_mask, att);
        // out projection + residual -> fp32 x
        hgemm<false, true, false><<<dim3(DD / 128, NROWS / 128), 256, TG_SMEM>>>(
            att, wt + W_OUT + (size_t)i * DD * DD, out_b + i * DD, x, x, DD, DD);
        ln_kernel<<<NROWS, 256>>>(x, n2_s + i * DD, n2_b + i * DD, h);
        // FF1 + relu -> half
        hgemm<true, false, true><<<dim3(DF / 128, NROWS / 128), 256, TG_SMEM>>>(
            h, wt + W_FF1 + (size_t)i * DD * DF, ff1_b + i * DF, nullptr, ff, DD, DF);
        // FF2 + residual -> fp32 x
        hgemm<false, true, false><<<dim3(DD / 128, NROWS / 128), 256, TG_SMEM>>>(
            ff, wt + W_FF2 + (size_t)i * DF * DD, ff2_b + i * DD, x, x, DF, DD);
    }

    head_kernel<<<BB, 256>>>(x, hln_s, hln_b, cls_w, cls_b, out);
}